// round 1
// baseline (speedup 1.0000x reference)
#include <cuda_runtime.h>
#include <cstdint>
#include <cstddef>

// Problem constants
#define BB    512
#define LL    200
#define DIMN  256
#define KCODE 2048
#define NROWS (BB * LL)      // 102400

// Argmin GEMM tiling
#define TM    64             // rows per CTA
#define TK    128            // codes per code-tile
#define RM    4              // rows per thread
#define RN    8              // codes per thread
#define KKD   (DIMN / 2)     // 128 packed k-pairs
#define CKK   8              // packed k-pairs per smem chunk (16 floats)
#define SUBS  (KKD / CKK)    // 16 chunks per code tile
#define NTILE (KCODE / TK)   // 16 code tiles
#define NCH   (NTILE * SUBS) // 256 chunks total
#define APITCH 66            // A smem pitch in doubles (64 + pad)
#define BPITCH 132           // B smem pitch in doubles (128 + pad)

__device__ float g_cnorm[KCODE];
__device__ int   g_idx[NROWS];

// ---------------------------------------------------------------------------
// Kernel 1: per-code squared norms ||c||^2  (one warp per code)
// ---------------------------------------------------------------------------
__global__ void cnorm_kernel(const float* __restrict__ cb) {
    int code = blockIdx.x * 8 + (threadIdx.x >> 5);
    int lane = threadIdx.x & 31;
    const float4* p = (const float4*)(cb + (size_t)code * DIMN);
    float s = 0.f;
#pragma unroll
    for (int i = 0; i < 2; i++) {
        float4 v = p[lane + 32 * i];
        s += v.x * v.x + v.y * v.y + v.z * v.z + v.w * v.w;
    }
#pragma unroll
    for (int o = 16; o; o >>= 1) s += __shfl_xor_sync(0xffffffffu, s, o);
    if (lane == 0) g_cnorm[code] = s;
}

// ---------------------------------------------------------------------------
// Kernel 2: argmin_k ( ||c_k||^2 - 2 * <e_r, c_k> )  for every row r.
// fp32 exact via packed fma.rn.f32x2 (Blackwell double-rate fp32 path).
// A tile (64 rows x 256 dims) resident in smem as interleaved k-pairs;
// codebook streamed in double-buffered chunks.
// ---------------------------------------------------------------------------
__global__ void __launch_bounds__(256)
argmin_kernel(const int* __restrict__ ids, const int* __restrict__ msk,
              const float* __restrict__ emb, const float* __restrict__ cb)
{
    extern __shared__ double sm[];
    double* Asd = sm;                       // [KKD][APITCH]
    double* Bsd = sm + KKD * APITCH;        // [2][CKK][BPITCH]

    const int tid = threadIdx.x;
    const int tx  = tid & 15;               // code group: codes tx + 16*j
    const int ty  = tid >> 4;               // row group:  rows  ty + 16*i
    const int r0  = blockIdx.x * TM;
    const double* cbd = (const double*)cb;

    // Load A tile (masked embedding rows), packed-pair layout As[kk][row]
    for (int p = 0; p < TM; p++) {
        int   id = ids[r0 + p];
        float m  = (msk[r0 + p] >= 1) ? 1.0f : 0.0f;
        float v  = emb[(size_t)id * DIMN + tid] * m;
        ((float*)sm)[((tid >> 1) * APITCH + p) * 2 + (tid & 1)] = v;
    }

    // B chunk loader mapping
    const int kkd  = tid & 7;               // 0..7  (packed-pair within chunk)
    const int cgrp = tid >> 3;              // 0..31 (code group)
    // prologue: chunk 0 (tile 0, sub 0) -> buffer 0
#pragma unroll
    for (int cc = 0; cc < 4; cc++) {
        int code = cgrp + cc * 32;
        Bsd[kkd * BPITCH + code] = cbd[(size_t)code * (DIMN / 2) + kkd];
    }

    unsigned long long acc[RM][RN];
#pragma unroll
    for (int i = 0; i < RM; i++)
#pragma unroll
        for (int j = 0; j < RN; j++) acc[i][j] = 0ull;

    float minv[RM];
    int   mini[RM];
#pragma unroll
    for (int i = 0; i < RM; i++) { minv[i] = 3.4e38f; mini[i] = 0; }

    __syncthreads();

    for (int ch = 0; ch < NCH; ch++) {
        const int buf  = ch & 1;
        const bool more = (ch + 1 < NCH);
        double pf[4];
        if (more) {
            const int nct  = (ch + 1) >> 4;
            const int nsub = (ch + 1) & 15;
#pragma unroll
            for (int cc = 0; cc < 4; cc++) {
                int code = cgrp + cc * 32;
                pf[cc] = cbd[(size_t)(nct * TK + code) * (DIMN / 2) + nsub * CKK + kkd];
            }
        }

        const double* Ab = Asd + (size_t)((ch & 15) * CKK) * APITCH + ty;
        const double* Bb = Bsd + (size_t)buf * (CKK * BPITCH) + tx;
#pragma unroll
        for (int kk = 0; kk < CKK; kk++) {
            unsigned long long av[RM], bv[RN];
#pragma unroll
            for (int i = 0; i < RM; i++)
                av[i] = *(const unsigned long long*)(Ab + kk * APITCH + i * 16);
#pragma unroll
            for (int j = 0; j < RN; j++)
                bv[j] = *(const unsigned long long*)(Bb + kk * BPITCH + j * 16);
#pragma unroll
            for (int i = 0; i < RM; i++)
#pragma unroll
                for (int j = 0; j < RN; j++)
                    asm("fma.rn.f32x2 %0, %1, %2, %0;"
                        : "+l"(acc[i][j]) : "l"(av[i]), "l"(bv[j]));
        }

        if (more) {
            double* Bn = Bsd + (size_t)(buf ^ 1) * (CKK * BPITCH);
#pragma unroll
            for (int cc = 0; cc < 4; cc++)
                Bn[kkd * BPITCH + cgrp + cc * 32] = pf[cc];
        }
        __syncthreads();

        if ((ch & 15) == 15) {   // finished a full code tile (all 256 dims)
            const int ct = ch >> 4;
#pragma unroll
            for (int i = 0; i < RM; i++) {
#pragma unroll
                for (int j = 0; j < RN; j++) {
                    float lo  = __uint_as_float((unsigned)acc[i][j]);
                    float hi  = __uint_as_float((unsigned)(acc[i][j] >> 32));
                    float dot = lo + hi;
                    int   code = ct * TK + tx + j * 16;
                    float dist = fmaf(-2.0f, dot, g_cnorm[code]);
                    if (dist < minv[i]) { minv[i] = dist; mini[i] = code; }
                    acc[i][j] = 0ull;
                }
            }
        }
    }

    // Reduce (min, argmin) across the 16 lanes sharing a ty group.
#pragma unroll
    for (int i = 0; i < RM; i++) {
        float v  = minv[i];
        int   ix = mini[i];
#pragma unroll
        for (int o = 8; o; o >>= 1) {
            float ov = __shfl_xor_sync(0xffffffffu, v,  o);
            int   oi = __shfl_xor_sync(0xffffffffu, ix, o);
            if (ov < v || (ov == v && oi < ix)) { v = ov; ix = oi; }
        }
        if (tx == 0) g_idx[r0 + ty + i * 16] = ix;
    }
}

// ---------------------------------------------------------------------------
// Kernel 3: per-batch means (vq_mean, hist_mean) fused with the encoder dense.
// One CTA per batch row; thread d owns output dim d.
// ---------------------------------------------------------------------------
__global__ void __launch_bounds__(256)
finish_kernel(const int* __restrict__ ids, const int* __restrict__ msk,
              const float* __restrict__ emb, const float* __restrict__ cb,
              const float* __restrict__ W,   const float* __restrict__ bias,
              float* __restrict__ out)
{
    __shared__ int   s_id[LL];
    __shared__ float s_m[LL];
    __shared__ int   s_vq[LL];
    __shared__ float s_x[2 * DIMN];
    __shared__ int   s_cnt;

    const int b = blockIdx.x, tid = threadIdx.x;
    if (tid == 0) s_cnt = 0;
    __syncthreads();
    if (tid < LL) {
        int   id = ids[b * LL + tid];
        float m  = (msk[b * LL + tid] >= 1) ? 1.f : 0.f;
        s_id[tid] = id;
        s_m[tid]  = m;
        s_vq[tid] = g_idx[b * LL + tid];
        if (m > 0.f) atomicAdd(&s_cnt, 1);
    }
    __syncthreads();

    const float cnt = (float)s_cnt;
    const int   d   = tid;          // 0..255
    float hist = 0.f, vq = 0.f;
    for (int l = 0; l < LL; l++) {
        if (s_m[l] != 0.f) hist += emb[(size_t)s_id[l] * DIMN + d];
        vq += cb[(size_t)s_vq[l] * DIMN + d];
    }
    s_x[d]        = vq / cnt;            // vq_mean (no eps, matches reference)
    s_x[DIMN + d] = hist / (cnt + 1e-9f);
    __syncthreads();

    float acc = bias[d];
#pragma unroll 8
    for (int i = 0; i < 2 * DIMN; i++)
        acc = fmaf(s_x[i], W[(size_t)i * DIMN + d], acc);
    out[(size_t)b * DIMN + d] = acc;
}

// ---------------------------------------------------------------------------
extern "C" void kernel_launch(void* const* d_in, const int* in_sizes, int n_in,
                              void* d_out, int out_size)
{
    const int*   ids  = (const int*)  d_in[0];
    const int*   msk  = (const int*)  d_in[1];
    const float* emb  = (const float*)d_in[2];
    const float* cb   = (const float*)d_in[3];
    const float* W    = (const float*)d_in[4];
    const float* bias = (const float*)d_in[5];
    float*       out  = (float*)d_out;

    const size_t smem = (size_t)(KKD * APITCH + 2 * CKK * BPITCH) * sizeof(double);
    cudaFuncSetAttribute(argmin_kernel,
                         cudaFuncAttributeMaxDynamicSharedMemorySize, (int)smem);

    cnorm_kernel<<<KCODE / 8, 256>>>(cb);
    argmin_kernel<<<NROWS / TM, 256, smem>>>(ids, msk, emb, cb);
    finish_kernel<<<BB, 256>>>(ids, msk, emb, cb, W, bias, out);
}

// round 3
// speedup vs baseline: 2.0703x; 2.0703x over previous
#include <cuda_runtime.h>
#include <cuda_bf16.h>
#include <cstdint>
#include <cstddef>

// ---------------------------------------------------------------- constants
#define BB    512
#define LL    200
#define DIMN  256
#define KCODE 2048
#define NROWS (BB * LL)          // 102400

#define MT    128                // rows per CTA
#define NTIL  64                 // codes per tile
#define NT    (KCODE / NTIL)     // 32 tiles
#define TILE_BYTES 65536         // 64 codes * 256 dims * 2B * (hi+lo)
#define HALF_TILE  32768
#define TAU   2.5e-4f            // rescore window (>> 50x error bound)

// smem layout
#define SO_BAR  0                // 2 mbarriers @ 0, 8
#define SO_CN   1024             // 8KB cnorm
#define SO_ALO  9216             // 64KB A-lo (128 rows x 256 dims bf16, swizzled)
#define SO_B    74752            // 2 x 64KB B tile buffers (hi|lo each)
#define SMEM_TOTAL (SO_B + 2 * TILE_BYTES)   // 205824

__device__ float  g_cnorm[KCODE];
__device__ int    g_idx[NROWS];
__device__ float4 g_meta[NROWS];
__device__ __align__(16) unsigned char g_btiles[NT * TILE_BYTES];  // 2MB pre-swizzled

// ---------------------------------------------------------------- PTX helpers
__device__ __forceinline__ uint32_t smem_u32(const void* p) {
    uint32_t a;
    asm("{ .reg .u64 t; cvta.to.shared.u64 t, %1; cvt.u32.u64 %0, t; }" : "=r"(a) : "l"(p));
    return a;
}
#define MBAR_INIT(a, n) asm volatile("mbarrier.init.shared.b64 [%0], %1;" :: "r"(a), "r"(n) : "memory")
#define MBAR_EXPECT_TX(a, b) asm volatile("mbarrier.arrive.expect_tx.shared.b64 _, [%0], %1;" :: "r"(a), "r"(b) : "memory")
#define MBAR_WAIT(a, p) do {                                                   \
    asm volatile("{\n\t.reg .pred P1;\n\tWL%=:\n\t"                            \
        "mbarrier.try_wait.parity.acquire.cta.shared::cta.b64 P1, [%0], %1, 0x989680;\n\t" \
        "@P1 bra.uni WD%=;\n\tbra.uni WL%=;\n\tWD%=:\n\t}"                     \
        :: "r"(a), "r"(p) : "memory");                                         \
} while (0)
#define BULK_G2S(dst, src, bytes, mbar)                                        \
    asm volatile("cp.async.bulk.shared::cta.global.mbarrier::complete_tx::bytes [%0], [%1], %2, [%3];" \
                 :: "r"(dst), "l"(src), "r"(bytes), "r"(mbar) : "memory")

#define LDSM_X4(r, a)                                                          \
    asm volatile("ldmatrix.sync.aligned.m8n8.x4.shared.b16 {%0,%1,%2,%3}, [%4];" \
        : "=r"((r)[0]), "=r"((r)[1]), "=r"((r)[2]), "=r"((r)[3]) : "r"(a))
#define LDSM_X2(r, a)                                                          \
    asm volatile("ldmatrix.sync.aligned.m8n8.x2.shared.b16 {%0,%1}, [%2];"     \
        : "=r"((r)[0]), "=r"((r)[1]) : "r"(a))

__device__ __forceinline__ void mma_bf16(float* d, const unsigned* a, const unsigned* b) {
    asm volatile("mma.sync.aligned.m16n8k16.row.col.f32.bf16.bf16.f32 "
        "{%0,%1,%2,%3}, {%4,%5,%6,%7}, {%8,%9}, {%0,%1,%2,%3};"
        : "+f"(d[0]), "+f"(d[1]), "+f"(d[2]), "+f"(d[3])
        : "r"(a[0]), "r"(a[1]), "r"(a[2]), "r"(a[3]), "r"(b[0]), "r"(b[1]));
}
__device__ __forceinline__ unsigned packbf(__nv_bfloat16 a, __nv_bfloat16 b) {
    return (unsigned)__bfloat16_as_ushort(a) | ((unsigned)__bfloat16_as_ushort(b) << 16);
}
__device__ __forceinline__ void ins2(float v, int i, float& v1, int& i1, float& v2, int& i2) {
    if (v < v1 || (v == v1 && i < i1)) { v2 = v1; i2 = i1; v1 = v; i1 = i; }
    else if (v < v2 || (v == v2 && i < i2)) { v2 = v; i2 = i; }
}

// ---------------------------------------------------------------- kernel 1: ||c||^2
__global__ void cnorm_kernel(const float* __restrict__ cb) {
    int code = blockIdx.x * 8 + (threadIdx.x >> 5);
    int lane = threadIdx.x & 31;
    const float4* p = (const float4*)(cb + (size_t)code * DIMN);
    float s = 0.f;
#pragma unroll
    for (int i = 0; i < 2; i++) {
        float4 v = p[lane + 32 * i];
        s += v.x * v.x + v.y * v.y + v.z * v.z + v.w * v.w;
    }
#pragma unroll
    for (int o = 16; o; o >>= 1) s += __shfl_xor_sync(0xffffffffu, s, o);
    if (lane == 0) g_cnorm[code] = s;
}

// ---------------------------------------------------------------- kernel 2: codebook hi/lo split
// into pre-swizzled tile images: tile = 64 codes; [hi 32KB | lo 32KB];
// within: addr = n*512 + d*2, XOR-swizzled by ((n&7)<<4).
__global__ void bsplit_kernel(const float* __restrict__ cb) {
    int idx = blockIdx.x * blockDim.x + threadIdx.x;   // 0 .. 2048*128-1
    int k  = idx >> 7;          // code
    int dp = idx & 127;         // dim pair
    float c0 = cb[(size_t)k * DIMN + 2 * dp];
    float c1 = cb[(size_t)k * DIMN + 2 * dp + 1];
    __nv_bfloat16 h0 = __float2bfloat16_rn(c0);
    __nv_bfloat16 h1 = __float2bfloat16_rn(c1);
    __nv_bfloat16 l0 = __float2bfloat16_rn(c0 - __bfloat162float(h0));
    __nv_bfloat16 l1 = __float2bfloat16_rn(c1 - __bfloat162float(h1));
    int tile = k >> 6, n = k & 63;
    uint32_t byte = (uint32_t)n * 512u + (uint32_t)dp * 4u;
    byte ^= (uint32_t)(n & 7) << 4;
    uint32_t addr = (uint32_t)tile * TILE_BYTES + byte;
    *(unsigned*)(g_btiles + addr)             = packbf(h0, h1);
    *(unsigned*)(g_btiles + addr + HALF_TILE) = packbf(l0, l1);
}

// ---------------------------------------------------------------- kernel 3: HMMA argmin
// acc[r][n] = (-2*mask*e_r).c_n via 3-term bf16 split; dist = ||c||^2 + acc; top-2/row.
__global__ void __launch_bounds__(256, 1)
argmin_mma(const int* __restrict__ ids, const int* __restrict__ msk,
           const float* __restrict__ emb)
{
    extern __shared__ char smem[];
    const uint32_t sb  = smem_u32(smem);
    const int tid = threadIdx.x;
    const int l   = tid & 31;
    const int w   = tid >> 5;
    const int r0  = blockIdx.x * MT;
    float* s_cn = (float*)(smem + SO_CN);

    if (tid == 0) { MBAR_INIT(sb + SO_BAR + 0, 1); MBAR_INIT(sb + SO_BAR + 8, 1); }

    // ---- stage A: 2 threads per row; hi -> B buf0 region (temp), lo -> SO_ALO
    {
        const int   row  = tid >> 1, half = tid & 1;
        const int   id   = ids[r0 + row];
        const float s    = (msk[r0 + row] >= 1) ? -2.0f : 0.0f;
        const float4* ep = (const float4*)(emb + (size_t)id * DIMN + half * 128);
        const uint32_t rowbase = (uint32_t)row * 512u;
        const uint32_t hb = (uint32_t)half * 256u;
        const uint32_t xo = (uint32_t)(row & 7) << 4;
#pragma unroll
        for (int q = 0; q < 32; q++) {
            float4 v = ep[q];
            float f0 = v.x * s, f1 = v.y * s, f2 = v.z * s, f3 = v.w * s;
            __nv_bfloat16 h0 = __float2bfloat16_rn(f0), h1 = __float2bfloat16_rn(f1);
            __nv_bfloat16 h2 = __float2bfloat16_rn(f2), h3 = __float2bfloat16_rn(f3);
            unsigned hiA = packbf(h0, h1), hiB = packbf(h2, h3);
            unsigned loA = packbf(__float2bfloat16_rn(f0 - __bfloat162float(h0)),
                                  __float2bfloat16_rn(f1 - __bfloat162float(h1)));
            unsigned loB = packbf(__float2bfloat16_rn(f2 - __bfloat162float(h2)),
                                  __float2bfloat16_rn(f3 - __bfloat162float(h3)));
            uint32_t off = rowbase + ((hb + (uint32_t)q * 8u) ^ xo);
            *(unsigned*)(smem + SO_B   + off)     = hiA;
            *(unsigned*)(smem + SO_B   + off + 4) = hiB;
            *(unsigned*)(smem + SO_ALO + off)     = loA;
            *(unsigned*)(smem + SO_ALO + off + 4) = loB;
        }
        for (int i = tid; i < KCODE; i += 256) s_cn[i] = g_cnorm[i];
    }
    __syncthreads();

    // ---- per-thread fragment address constants
    const uint32_t xorv   = (uint32_t)(l & 7) << 4;
    const uint32_t arow   = (uint32_t)(w * 16 + (l & 7) + ((l >> 3) & 1) * 8);
    const uint32_t koff_a = (uint32_t)((l >> 4) & 1) * 16u;
    const uint32_t koff_b = (uint32_t)((l & 15) >> 3) * 16u;
    const uint32_t bnb    = (uint32_t)(l & 7) * 512u;
    const uint32_t a_hi_b = sb + SO_B   + arow * 512u;
    const uint32_t a_lo_b = sb + SO_ALO + arow * 512u;

    // ---- A-hi fragments -> persistent registers (64 regs)
    unsigned ah[16][4];
#pragma unroll
    for (int s = 0; s < 16; s++)
        LDSM_X4(ah[s], a_hi_b + (((uint32_t)(s * 32) + koff_a) ^ xorv));
    __syncthreads();   // staging region free -> becomes B buf0

    if (tid == 0) {
        MBAR_EXPECT_TX(sb + SO_BAR + 0, TILE_BYTES);
        BULK_G2S(sb + SO_B, (const void*)g_btiles, TILE_BYTES, sb + SO_BAR + 0);
        MBAR_EXPECT_TX(sb + SO_BAR + 8, TILE_BYTES);
        BULK_G2S(sb + SO_B + TILE_BYTES, (const void*)(g_btiles + TILE_BYTES),
                 TILE_BYTES, sb + SO_BAR + 8);
    }

    float acc[8][4];
#pragma unroll
    for (int j = 0; j < 8; j++)
#pragma unroll
        for (int e = 0; e < 4; e++) acc[j][e] = 0.f;

    float v1[2] = {3.4e38f, 3.4e38f}, v2[2] = {3.4e38f, 3.4e38f};
    int   i1[2] = {0, 0},             i2[2] = {0, 0};
    int par[2] = {0, 0};

    for (int t = 0; t < NT; t++) {
        const int buf = t & 1;
        const uint32_t Bb = sb + SO_B + (uint32_t)buf * TILE_BYTES;
        MBAR_WAIT(sb + SO_BAR + 8 * buf, (uint32_t)par[buf]); par[buf] ^= 1;

#pragma unroll
        for (int s = 0; s < 16; s++) {
            unsigned al[4];
            LDSM_X4(al, a_lo_b + (((uint32_t)(s * 32) + koff_a) ^ xorv));
            const uint32_t kx = ((uint32_t)(s * 32) + koff_b) ^ xorv;
#pragma unroll
            for (int j = 0; j < 8; j++) {
                unsigned bh[2], bl[2];
                LDSM_X2(bh, Bb + (uint32_t)j * 4096u + bnb + kx);
                LDSM_X2(bl, Bb + HALF_TILE + (uint32_t)j * 4096u + bnb + kx);
                mma_bf16(acc[j], ah[s], bh);
                mma_bf16(acc[j], al,    bh);
                mma_bf16(acc[j], ah[s], bl);
            }
        }

        // epilogue: dist = ||c||^2 + acc, per-thread top-2 (rows l/4 and l/4+8)
        const int cbase = t * NTIL;
#pragma unroll
        for (int j = 0; j < 8; j++) {
#pragma unroll
            for (int e = 0; e < 4; e++) {
                const int rr   = e >> 1;
                const int code = cbase + j * 8 + 2 * (l & 3) + (e & 1);
                const float dist = s_cn[code] + acc[j][e];
                ins2(dist, code, v1[rr], i1[rr], v2[rr], i2[rr]);
                acc[j][e] = 0.f;
            }
        }
        __syncthreads();
        if (tid == 0 && t + 2 < NT) {
            MBAR_EXPECT_TX(sb + SO_BAR + 8 * buf, TILE_BYTES);
            BULK_G2S(Bb, (const void*)(g_btiles + (size_t)(t + 2) * TILE_BYTES),
                     TILE_BYTES, sb + SO_BAR + 8 * buf);
        }
    }

    // ---- reduce top-2 across the 4 lanes of each row quad
#pragma unroll
    for (int rr = 0; rr < 2; rr++) {
#pragma unroll
        for (int off = 1; off <= 2; off <<= 1) {
            float ov1 = __shfl_xor_sync(0xffffffffu, v1[rr], off);
            int   oi1 = __shfl_xor_sync(0xffffffffu, i1[rr], off);
            float ov2 = __shfl_xor_sync(0xffffffffu, v2[rr], off);
            int   oi2 = __shfl_xor_sync(0xffffffffu, i2[rr], off);
            ins2(ov1, oi1, v1[rr], i1[rr], v2[rr], i2[rr]);
            ins2(ov2, oi2, v1[rr], i1[rr], v2[rr], i2[rr]);
        }
        if ((l & 3) == 0) {
            const int grow = r0 + w * 16 + (l >> 2) + rr * 8;
            g_idx[grow]  = i1[rr];
            g_meta[grow] = make_float4(v1[rr], v2[rr],
                                       __int_as_float(i1[rr]), __int_as_float(i2[rr]));
        }
    }
}

// ---------------------------------------------------------------- kernel 4: exact rescore of near-ties
__global__ void rescore_kernel(const int* __restrict__ ids, const int* __restrict__ msk,
                               const float* __restrict__ emb, const float* __restrict__ cb)
{
    int r = blockIdx.x * blockDim.x + threadIdx.x;
    if (r >= NROWS) return;
    float4 m = g_meta[r];
    if (m.y - m.x >= TAU) return;
    int i1 = __float_as_int(m.z), i2 = __float_as_int(m.w);
    int   id = ids[r];
    float s  = (msk[r] >= 1) ? 1.0f : 0.0f;
    const float* e  = emb + (size_t)id * DIMN;
    const float* c1 = cb + (size_t)i1 * DIMN;
    const float* c2 = cb + (size_t)i2 * DIMN;
    float a1 = 0.f, b1 = 0.f, a2 = 0.f, b2 = 0.f;
#pragma unroll 4
    for (int k = 0; k < DIMN; k += 2) {
        float e0 = e[k] * s, e1 = e[k + 1] * s;
        a1 = fmaf(e0, c1[k], a1); b1 = fmaf(e1, c1[k + 1], b1);
        a2 = fmaf(e0, c2[k], a2); b2 = fmaf(e1, c2[k + 1], b2);
    }
    float d1 = fmaf(-2.0f, a1 + b1, g_cnorm[i1]);
    float d2 = fmaf(-2.0f, a2 + b2, g_cnorm[i2]);
    int best;
    if (d1 < d2)      best = i1;
    else if (d2 < d1) best = i2;
    else              best = (i1 < i2) ? i1 : i2;
    g_idx[r] = best;
}

// ---------------------------------------------------------------- kernel 5: means + encoder dense
__global__ void __launch_bounds__(256)
finish_kernel(const int* __restrict__ ids, const int* __restrict__ msk,
              const float* __restrict__ emb, const float* __restrict__ cb,
              const float* __restrict__ W,   const float* __restrict__ bias,
              float* __restrict__ out)
{
    __shared__ int   s_id[LL];
    __shared__ float s_m[LL];
    __shared__ int   s_vq[LL];
    __shared__ float s_x[2 * DIMN];
    __shared__ int   s_cnt;

    const int b = blockIdx.x, tid = threadIdx.x;
    if (tid == 0) s_cnt = 0;
    __syncthreads();
    if (tid < LL) {
        int   id = ids[b * LL + tid];
        float m  = (msk[b * LL + tid] >= 1) ? 1.f : 0.f;
        s_id[tid] = id;
        s_m[tid]  = m;
        s_vq[tid] = g_idx[b * LL + tid];
        if (m > 0.f) atomicAdd(&s_cnt, 1);
    }
    __syncthreads();

    const float cnt = (float)s_cnt;
    const int   d   = tid;
    float hist = 0.f, vq = 0.f;
    for (int ll = 0; ll < LL; ll++) {
        if (s_m[ll] != 0.f) hist += emb[(size_t)s_id[ll] * DIMN + d];
        vq += cb[(size_t)s_vq[ll] * DIMN + d];
    }
    s_x[d]        = vq / cnt;
    s_x[DIMN + d] = hist / (cnt + 1e-9f);
    __syncthreads();

    float acc = bias[d];
#pragma unroll 8
    for (int i = 0; i < 2 * DIMN; i++)
        acc = fmaf(s_x[i], W[(size_t)i * DIMN + d], acc);
    out[(size_t)b * DIMN + d] = acc;
}

// ----------------------------------------------------------------
extern "C" void kernel_launch(void* const* d_in, const int* in_sizes, int n_in,
                              void* d_out, int out_size)
{
    const int*   ids  = (const int*)  d_in[0];
    const int*   msk  = (const int*)  d_in[1];
    const float* emb  = (const float*)d_in[2];
    const float* cb   = (const float*)d_in[3];
    const float* W    = (const float*)d_in[4];
    const float* bias = (const float*)d_in[5];
    float*       out  = (float*)d_out;

    cudaFuncSetAttribute(argmin_mma,
                         cudaFuncAttributeMaxDynamicSharedMemorySize, SMEM_TOTAL);

    cnorm_kernel<<<KCODE / 8, 256>>>(cb);
    bsplit_kernel<<<(KCODE * (DIMN / 2)) / 256, 256>>>(cb);
    argmin_mma<<<NROWS / MT, 256, SMEM_TOTAL>>>(ids, msk, emb);
    rescore_kernel<<<(NROWS + 255) / 256, 256>>>(ids, msk, emb, cb);
    finish_kernel<<<BB, 256>>>(ids, msk, emb, cb, W, bias, out);
}

// round 4
// speedup vs baseline: 3.5029x; 1.6920x over previous
#include <cuda_runtime.h>
#include <cuda_fp16.h>
#include <cstdint>
#include <cstddef>

// ---------------------------------------------------------------- constants
#define BB    512
#define LL    200
#define DIMN  256
#define KCODE 2048
#define NROWS (BB * LL)          // 102400

#define MT    128                // rows per CTA
#define NTIL  64                 // codes per tile
#define NT    (KCODE / NTIL)     // 32 tiles
#define TILE_BYTES 32768         // 64 codes * 256 dims * 2B fp16
#define TAU   4e-3f              // rescore window (~10 sigma of fp16 dist error)

// smem layout (argmin kernel)
#define SO_BAR  0                // 2 mbarriers @ 0, 8
#define SO_MAP  64               // 128 ints (row map slice)
#define SO_CN   1024             // 8KB cnorm
#define SO_B    9216             // 2 x 32KB B tile buffers (1KB aligned)
#define SMEM_TOTAL (SO_B + 2 * TILE_BYTES)   // 74752

__device__ float  g_cnorm[KCODE];
__device__ int    g_idx[NROWS];
__device__ float2 g_meta[NROWS];
__device__ int4   g_cand[NROWS];
__device__ int    g_rowmap[NROWS];
__device__ int    g_nvalid;
__device__ int    g_c0;
__device__ __align__(16) unsigned char g_btiles[NT * TILE_BYTES];  // 1MB fp16 pre-swizzled

// ---------------------------------------------------------------- PTX helpers
__device__ __forceinline__ uint32_t smem_u32(const void* p) {
    uint32_t a;
    asm("{ .reg .u64 t; cvta.to.shared.u64 t, %1; cvt.u32.u64 %0, t; }" : "=r"(a) : "l"(p));
    return a;
}
#define MBAR_INIT(a, n) asm volatile("mbarrier.init.shared.b64 [%0], %1;" :: "r"(a), "r"(n) : "memory")
#define MBAR_EXPECT_TX(a, b) asm volatile("mbarrier.arrive.expect_tx.shared.b64 _, [%0], %1;" :: "r"(a), "r"(b) : "memory")
#define MBAR_WAIT(a, p) do {                                                   \
    asm volatile("{\n\t.reg .pred P1;\n\tWL%=:\n\t"                            \
        "mbarrier.try_wait.parity.acquire.cta.shared::cta.b64 P1, [%0], %1, 0x989680;\n\t" \
        "@P1 bra.uni WD%=;\n\tbra.uni WL%=;\n\tWD%=:\n\t}"                     \
        :: "r"(a), "r"(p) : "memory");                                         \
} while (0)
#define BULK_G2S(dst, src, bytes, mbar)                                        \
    asm volatile("cp.async.bulk.shared::cta.global.mbarrier::complete_tx::bytes [%0], [%1], %2, [%3];" \
                 :: "r"(dst), "l"(src), "r"(bytes), "r"(mbar) : "memory")

#define LDSM_X4(r, a)                                                          \
    asm volatile("ldmatrix.sync.aligned.m8n8.x4.shared.b16 {%0,%1,%2,%3}, [%4];" \
        : "=r"((r)[0]), "=r"((r)[1]), "=r"((r)[2]), "=r"((r)[3]) : "r"(a))

__device__ __forceinline__ void mma_f16(float* d, const unsigned* a, const unsigned* b) {
    asm volatile("mma.sync.aligned.m16n8k16.row.col.f32.f16.f16.f32 "
        "{%0,%1,%2,%3}, {%4,%5,%6,%7}, {%8,%9}, {%0,%1,%2,%3};"
        : "+f"(d[0]), "+f"(d[1]), "+f"(d[2]), "+f"(d[3])
        : "r"(a[0]), "r"(a[1]), "r"(a[2]), "r"(a[3]), "r"(b[0]), "r"(b[1]));
}
__device__ __forceinline__ unsigned packh(float a, float b) {
    __half2 h = __floats2half2_rn(a, b);
    return *reinterpret_cast<unsigned*>(&h);
}
// lexicographic sorted-insert into ascending top-4
__device__ __forceinline__ void ins4(float d, int c, float v[4], int ix[4]) {
#pragma unroll
    for (int q = 0; q < 4; q++) {
        bool lt = (d < v[q]) || (d == v[q] && c < ix[q]);
        float tv = lt ? d : v[q];  int ti = lt ? c : ix[q];
        float nd = lt ? v[q] : d;  int nc = lt ? ix[q] : c;
        v[q] = tv; ix[q] = ti; d = nd; c = nc;
    }
}

// ---------------------------------------------------------------- kernel 1: ||c||^2
__global__ void cnorm_kernel(const float* __restrict__ cb) {
    int code = blockIdx.x * 8 + (threadIdx.x >> 5);
    int lane = threadIdx.x & 31;
    const float4* p = (const float4*)(cb + (size_t)code * DIMN);
    float s = 0.f;
#pragma unroll
    for (int i = 0; i < 2; i++) {
        float4 v = p[lane + 32 * i];
        s += v.x * v.x + v.y * v.y + v.z * v.z + v.w * v.w;
    }
#pragma unroll
    for (int o = 16; o; o >>= 1) s += __shfl_xor_sync(0xffffffffu, s, o);
    if (lane == 0) g_cnorm[code] = s;
}

// ---------------------------------------------------------------- kernel 2: fp16 codebook tiles
// (also initializes rowmap to -1). tile image: code n at n*512 + (d*2 ^ ((n&7)<<4))
__global__ void bsplit_kernel(const float* __restrict__ cb) {
    int idx = blockIdx.x * blockDim.x + threadIdx.x;   // 0 .. 262143
    if (idx < NROWS) g_rowmap[idx] = -1;
    int k  = idx >> 7;          // code
    int dp = idx & 127;         // dim pair
    float c0 = cb[(size_t)k * DIMN + 2 * dp];
    float c1 = cb[(size_t)k * DIMN + 2 * dp + 1];
    int tile = k >> 6, n = k & 63;
    uint32_t byte = (uint32_t)n * 512u + (uint32_t)dp * 4u;
    byte ^= (uint32_t)(n & 7) << 4;
    *(unsigned*)(g_btiles + (uint32_t)tile * TILE_BYTES + byte) = packh(c0, c1);
}

// ---------------------------------------------------------------- kernel 3: c0 = argmin ||c||^2, reset counter
__global__ void prep_kernel() {
    __shared__ float sv[8];
    __shared__ int   si[8];
    int tid = threadIdx.x;
    float v = 3.4e38f; int ix = 0x7fffffff;
    for (int i = tid; i < KCODE; i += 256) {
        float c = g_cnorm[i];
        if (c < v || (c == v && i < ix)) { v = c; ix = i; }
    }
#pragma unroll
    for (int o = 16; o; o >>= 1) {
        float ov = __shfl_xor_sync(0xffffffffu, v, o);
        int   oi = __shfl_xor_sync(0xffffffffu, ix, o);
        if (ov < v || (ov == v && oi < ix)) { v = ov; ix = oi; }
    }
    if ((tid & 31) == 0) { sv[tid >> 5] = v; si[tid >> 5] = ix; }
    __syncthreads();
    if (tid == 0) {
#pragma unroll
        for (int q = 1; q < 8; q++)
            if (sv[q] < v || (sv[q] == v && si[q] < ix)) { v = sv[q]; ix = si[q]; }
        g_c0 = ix;
        g_nvalid = 0;
    }
}

// ---------------------------------------------------------------- kernel 4: compact valid rows
__global__ void compact_kernel(const int* __restrict__ msk) {
    int r = blockIdx.x * blockDim.x + threadIdx.x;
    if (r >= NROWS) return;
    if (msk[r] >= 1) {
        int pos = atomicAdd(&g_nvalid, 1);
        g_rowmap[pos] = r;
    } else {
        g_idx[r] = g_c0;   // masked row: e = 0 -> argmin ||c||^2
    }
}

// ---------------------------------------------------------------- kernel 5: fp16 HMMA argmin (valid rows)
// acc[r][n] = <e_r, c_n>; dist = ||c||^2 - 2*acc; top-4 per row; exact rescore later.
__global__ void __launch_bounds__(256, 1)
argmin_mma(const int* __restrict__ ids, const float* __restrict__ emb)
{
    extern __shared__ char smem[];
    const uint32_t sb  = smem_u32(smem);
    const int tid = threadIdx.x;
    const int l   = tid & 31;
    const int w   = tid >> 5;
    const int r0  = blockIdx.x * MT;
    if (r0 >= g_nvalid) return;                 // whole-CTA early exit
    float* s_cn  = (float*)(smem + SO_CN);
    int*   s_map = (int*)(smem + SO_MAP);

    if (tid == 0) { MBAR_INIT(sb + SO_BAR + 0, 1); MBAR_INIT(sb + SO_BAR + 8, 1); }

    // ---- stage A rows (fp16) into the B-buffer region temporarily
    {
        const int row  = tid >> 1, half = tid & 1;
        int X = g_rowmap[r0 + row];
        if (X < 0) X = g_rowmap[0];             // tail padding -> duplicate a valid row
        if (half == 0) s_map[row] = X;
        const int id = ids[X];
        const float4* ep = (const float4*)(emb + (size_t)id * DIMN + half * 128);
        const uint32_t rowbase = (uint32_t)row * 512u;
        const uint32_t hb = (uint32_t)half * 256u;
        const uint32_t xo = (uint32_t)(row & 7) << 4;
#pragma unroll
        for (int q = 0; q < 32; q++) {
            float4 v = ep[q];
            uint32_t off = rowbase + ((hb + (uint32_t)q * 8u) ^ xo);
            *(unsigned*)(smem + SO_B + off)     = packh(v.x, v.y);
            *(unsigned*)(smem + SO_B + off + 4) = packh(v.z, v.w);
        }
        for (int i = tid; i < KCODE; i += 256) s_cn[i] = g_cnorm[i];
    }
    __syncthreads();

    // ---- fragment address constants
    const uint32_t xorv   = (uint32_t)(l & 7) << 4;
    const uint32_t arow   = (uint32_t)(w * 16 + (l & 7) + ((l >> 3) & 1) * 8);
    const uint32_t koff_a = (uint32_t)((l >> 4) & 1) * 16u;
    const uint32_t jpoff  = (uint32_t)((l >> 4) & 1) * 4096u + (uint32_t)(l & 7) * 512u;
    const uint32_t koff_b = (uint32_t)((l >> 3) & 1) * 16u;

    // ---- A fragments -> persistent registers (64 regs)
    unsigned ah[16][4];
    {
        const uint32_t a_b = sb + SO_B + arow * 512u;
#pragma unroll
        for (int s = 0; s < 16; s++)
            LDSM_X4(ah[s], a_b + (((uint32_t)(s * 32) + koff_a) ^ xorv));
    }
    __syncthreads();   // staging free -> becomes B double buffer

    if (tid == 0) {
        MBAR_EXPECT_TX(sb + SO_BAR + 0, TILE_BYTES);
        BULK_G2S(sb + SO_B, (const void*)g_btiles, TILE_BYTES, sb + SO_BAR + 0);
        MBAR_EXPECT_TX(sb + SO_BAR + 8, TILE_BYTES);
        BULK_G2S(sb + SO_B + TILE_BYTES, (const void*)(g_btiles + TILE_BYTES),
                 TILE_BYTES, sb + SO_BAR + 8);
    }

    float acc[8][4];
#pragma unroll
    for (int j = 0; j < 8; j++)
#pragma unroll
        for (int e = 0; e < 4; e++) acc[j][e] = 0.f;

    float v4[2][4]; int ix4[2][4];
#pragma unroll
    for (int rr = 0; rr < 2; rr++)
#pragma unroll
        for (int q = 0; q < 4; q++) { v4[rr][q] = 3.4e38f; ix4[rr][q] = 0x7fffffff; }

    int par[2] = {0, 0};

    for (int t = 0; t < NT; t++) {
        const int buf = t & 1;
        const uint32_t Bb = sb + SO_B + (uint32_t)buf * TILE_BYTES;
        MBAR_WAIT(sb + SO_BAR + 8 * buf, (uint32_t)par[buf]); par[buf] ^= 1;

#pragma unroll
        for (int s = 0; s < 16; s++) {
            const uint32_t kx = ((uint32_t)(s * 32) + koff_b) ^ xorv;
#pragma unroll
            for (int p = 0; p < 4; p++) {        // p covers code pairs (2p, 2p+1)
                unsigned b4[4];
                LDSM_X4(b4, Bb + jpoff + (uint32_t)p * 8192u + kx);
                mma_f16(acc[2 * p],     ah[s], b4);
                mma_f16(acc[2 * p + 1], ah[s], b4 + 2);
            }
        }

        // epilogue: dist = ||c||^2 - 2*acc; top-4 per row (guarded insert)
        const int cbase = t * NTIL;
#pragma unroll
        for (int j = 0; j < 8; j++) {
#pragma unroll
            for (int e = 0; e < 4; e++) {
                const int rr   = e >> 1;
                const int code = cbase + j * 8 + 2 * (l & 3) + (e & 1);
                const float dist = fmaf(-2.0f, acc[j][e], s_cn[code]);
                if (dist < v4[rr][3]) ins4(dist, code, v4[rr], ix4[rr]);
                acc[j][e] = 0.f;
            }
        }
        __syncthreads();
        if (tid == 0 && t + 2 < NT) {
            MBAR_EXPECT_TX(sb + SO_BAR + 8 * buf, TILE_BYTES);
            BULK_G2S(Bb, (const void*)(g_btiles + (size_t)(t + 2) * TILE_BYTES),
                     TILE_BYTES, sb + SO_BAR + 8 * buf);
        }
    }

    // ---- merge top-4 across the 4 lanes sharing each row
#pragma unroll
    for (int rr = 0; rr < 2; rr++) {
#pragma unroll
        for (int off = 1; off <= 2; off <<= 1) {
            float ov[4]; int oi[4];
#pragma unroll
            for (int q = 0; q < 4; q++) {
                ov[q] = __shfl_xor_sync(0xffffffffu, v4[rr][q], off);
                oi[q] = __shfl_xor_sync(0xffffffffu, ix4[rr][q], off);
            }
#pragma unroll
            for (int q = 0; q < 4; q++) ins4(ov[q], oi[q], v4[rr], ix4[rr]);
        }
        if ((l & 3) == 0) {
            const int X = s_map[w * 16 + (l >> 2) + rr * 8];
            g_idx[X]  = ix4[rr][0];
            g_meta[X] = make_float2(v4[rr][0], v4[rr][1]);
            g_cand[X] = make_int4(ix4[rr][0], ix4[rr][1], ix4[rr][2], ix4[rr][3]);
        }
    }
}

// ---------------------------------------------------------------- kernel 6: exact fp32 rescore of near-ties
__global__ void rescore_kernel(const int* __restrict__ ids, const int* __restrict__ msk,
                               const float* __restrict__ emb, const float* __restrict__ cb)
{
    int r = blockIdx.x * blockDim.x + threadIdx.x;
    if (r >= NROWS) return;
    if (msk[r] < 1) return;
    float2 m = g_meta[r];
    if (m.y - m.x >= TAU) return;
    int4 cd = g_cand[r];
    const int cods[4] = {cd.x, cd.y, cd.z, cd.w};
    const float* e = emb + (size_t)ids[r] * DIMN;

    float bestd = 3.4e38f; int besti = 0x7fffffff;
#pragma unroll
    for (int q = 0; q < 4; q++) {
        const int c = cods[q];
        const float* cp = cb + (size_t)c * DIMN;
        float a = 0.f, b = 0.f;
#pragma unroll 4
        for (int k = 0; k < DIMN; k += 2) {
            a = fmaf(e[k],     cp[k],     a);
            b = fmaf(e[k + 1], cp[k + 1], b);
        }
        float d = fmaf(-2.0f, a + b, g_cnorm[c]);
        if (d < bestd || (d == bestd && c < besti)) { bestd = d; besti = c; }
    }
    g_idx[r] = besti;
}

// ---------------------------------------------------------------- kernel 7: means + encoder dense
__global__ void __launch_bounds__(256)
finish_kernel(const int* __restrict__ ids, const int* __restrict__ msk,
              const float* __restrict__ emb, const float* __restrict__ cb,
              const float* __restrict__ W,   const float* __restrict__ bias,
              float* __restrict__ out)
{
    __shared__ int   s_id[LL];
    __shared__ float s_m[LL];
    __shared__ int   s_vq[LL];
    __shared__ float s_x[2 * DIMN];
    __shared__ int   s_cnt;

    const int b = blockIdx.x, tid = threadIdx.x;
    if (tid == 0) s_cnt = 0;
    __syncthreads();
    if (tid < LL) {
        int   id = ids[b * LL + tid];
        float m  = (msk[b * LL + tid] >= 1) ? 1.f : 0.f;
        s_id[tid] = id;
        s_m[tid]  = m;
        s_vq[tid] = g_idx[b * LL + tid];
        if (m > 0.f) atomicAdd(&s_cnt, 1);
    }
    __syncthreads();

    const float cnt = (float)s_cnt;
    const int   d   = tid;
    float hist = 0.f, vq = 0.f;
    for (int ll = 0; ll < LL; ll++) {
        if (s_m[ll] != 0.f) hist += emb[(size_t)s_id[ll] * DIMN + d];
        vq += cb[(size_t)s_vq[ll] * DIMN + d];
    }
    s_x[d]        = vq / cnt;
    s_x[DIMN + d] = hist / (cnt + 1e-9f);
    __syncthreads();

    float acc = bias[d];
#pragma unroll 8
    for (int i = 0; i < 2 * DIMN; i++)
        acc = fmaf(s_x[i], W[(size_t)i * DIMN + d], acc);
    out[(size_t)b * DIMN + d] = acc;
}

// ----------------------------------------------------------------
extern "C" void kernel_launch(void* const* d_in, const int* in_sizes, int n_in,
                              void* d_out, int out_size)
{
    const int*   ids  = (const int*)  d_in[0];
    const int*   msk  = (const int*)  d_in[1];
    const float* emb  = (const float*)d_in[2];
    const float* cb   = (const float*)d_in[3];
    const float* W    = (const float*)d_in[4];
    const float* bias = (const float*)d_in[5];
    float*       out  = (float*)d_out;

    cudaFuncSetAttribute(argmin_mma,
                         cudaFuncAttributeMaxDynamicSharedMemorySize, SMEM_TOTAL);

    cnorm_kernel<<<KCODE / 8, 256>>>(cb);
    bsplit_kernel<<<(KCODE * (DIMN / 2)) / 256, 256>>>(cb);   // also inits rowmap
    prep_kernel<<<1, 256>>>();                                 // c0 + counter reset
    compact_kernel<<<(NROWS + 255) / 256, 256>>>(msk);
    argmin_mma<<<NROWS / MT, 256, SMEM_TOTAL>>>(ids, emb);
    rescore_kernel<<<(NROWS + 255) / 256, 256>>>(ids, msk, emb, cb);
    finish_kernel<<<BB, 256>>>(ids, msk, emb, cb, W, bias, out);
}

// round 5
// speedup vs baseline: 5.6374x; 1.6094x over previous
#include <cuda_runtime.h>
#include <cuda_fp16.h>
#include <cstdint>
#include <cstddef>

// ---------------------------------------------------------------- constants
#define BB    512
#define LL    200
#define DIMN  256
#define KCODE 2048
#define NROWS (BB * LL)          // 102400
#define VOCAB 100000

#define MT    128                // unique ids per CTA
#define NTIL  64                 // codes per tile
#define NT    (KCODE / NTIL)     // 32 tiles
#define TILE_BYTES 32768         // 64 codes * 256 dims * 2B fp16
#define TAU   4e-3f              // rescore window (~10 sigma of fp16 dist error)
#define MAXCTA ((VOCAB + MT - 1) / MT)   // 782

// smem layout (argmin kernel)
#define SO_BAR  0                // 2 mbarriers @ 0, 8
#define SO_MAP  64               // 128 ints (unique-id slice)
#define SO_CN   1024             // 8KB cnorm
#define SO_B    9216             // 2 x 32KB B tile buffers (1KB aligned)
#define SMEM_TOTAL (SO_B + 2 * TILE_BYTES)   // 74752

__device__ float  g_cnorm[KCODE];
__device__ int    g_mark[VOCAB];
__device__ int    g_uniq[VOCAB];
__device__ int    g_nuniq;
__device__ int    g_c0;
__device__ int    g_ridx[VOCAB];         // per-id argmin result
__device__ float2 g_rmeta[VOCAB];
__device__ int4   g_rcand[VOCAB];
__device__ __align__(16) unsigned char g_btiles[NT * TILE_BYTES];  // 1MB fp16 pre-swizzled

// ---------------------------------------------------------------- PTX helpers
__device__ __forceinline__ uint32_t smem_u32(const void* p) {
    uint32_t a;
    asm("{ .reg .u64 t; cvta.to.shared.u64 t, %1; cvt.u32.u64 %0, t; }" : "=r"(a) : "l"(p));
    return a;
}
#define MBAR_INIT(a, n) asm volatile("mbarrier.init.shared.b64 [%0], %1;" :: "r"(a), "r"(n) : "memory")
#define MBAR_EXPECT_TX(a, b) asm volatile("mbarrier.arrive.expect_tx.shared.b64 _, [%0], %1;" :: "r"(a), "r"(b) : "memory")
#define MBAR_WAIT(a, p) do {                                                   \
    asm volatile("{\n\t.reg .pred P1;\n\tWL%=:\n\t"                            \
        "mbarrier.try_wait.parity.acquire.cta.shared::cta.b64 P1, [%0], %1, 0x989680;\n\t" \
        "@P1 bra.uni WD%=;\n\tbra.uni WL%=;\n\tWD%=:\n\t}"                     \
        :: "r"(a), "r"(p) : "memory");                                         \
} while (0)
#define BULK_G2S(dst, src, bytes, mbar)                                        \
    asm volatile("cp.async.bulk.shared::cta.global.mbarrier::complete_tx::bytes [%0], [%1], %2, [%3];" \
                 :: "r"(dst), "l"(src), "r"(bytes), "r"(mbar) : "memory")

#define LDSM_X4(r, a)                                                          \
    asm volatile("ldmatrix.sync.aligned.m8n8.x4.shared.b16 {%0,%1,%2,%3}, [%4];" \
        : "=r"((r)[0]), "=r"((r)[1]), "=r"((r)[2]), "=r"((r)[3]) : "r"(a))

__device__ __forceinline__ void mma_f16(float* d, const unsigned* a, const unsigned* b) {
    asm volatile("mma.sync.aligned.m16n8k16.row.col.f32.f16.f16.f32 "
        "{%0,%1,%2,%3}, {%4,%5,%6,%7}, {%8,%9}, {%0,%1,%2,%3};"
        : "+f"(d[0]), "+f"(d[1]), "+f"(d[2]), "+f"(d[3])
        : "r"(a[0]), "r"(a[1]), "r"(a[2]), "r"(a[3]), "r"(b[0]), "r"(b[1]));
}
__device__ __forceinline__ unsigned packh(float a, float b) {
    __half2 h = __floats2half2_rn(a, b);
    return *reinterpret_cast<unsigned*>(&h);
}
// lexicographic sorted-insert into ascending top-4
__device__ __forceinline__ void ins4(float d, int c, float v[4], int ix[4]) {
#pragma unroll
    for (int q = 0; q < 4; q++) {
        bool lt = (d < v[q]) || (d == v[q] && c < ix[q]);
        float tv = lt ? d : v[q];  int ti = lt ? c : ix[q];
        float nd = lt ? v[q] : d;  int nc = lt ? ix[q] : c;
        v[q] = tv; ix[q] = ti; d = nd; c = nc;
    }
}

// ---------------------------------------------------------------- kernel 1: ||c||^2
__global__ void cnorm_kernel(const float* __restrict__ cb) {
    int code = blockIdx.x * 8 + (threadIdx.x >> 5);
    int lane = threadIdx.x & 31;
    const float4* p = (const float4*)(cb + (size_t)code * DIMN);
    float s = 0.f;
#pragma unroll
    for (int i = 0; i < 2; i++) {
        float4 v = p[lane + 32 * i];
        s += v.x * v.x + v.y * v.y + v.z * v.z + v.w * v.w;
    }
#pragma unroll
    for (int o = 16; o; o >>= 1) s += __shfl_xor_sync(0xffffffffu, s, o);
    if (lane == 0) g_cnorm[code] = s;
}

// ---------------------------------------------------------------- kernel 2: fp16 codebook tiles
// (also zeroes the dedup mark array + counter). code n at n*512 + (d*2 ^ ((n&7)<<4))
__global__ void bsplit_kernel(const float* __restrict__ cb) {
    int idx = blockIdx.x * blockDim.x + threadIdx.x;   // 0 .. 262143
    if (idx < VOCAB) g_mark[idx] = 0;
    if (idx == 0) g_nuniq = 0;
    int k  = idx >> 7;          // code
    int dp = idx & 127;         // dim pair
    float c0 = cb[(size_t)k * DIMN + 2 * dp];
    float c1 = cb[(size_t)k * DIMN + 2 * dp + 1];
    int tile = k >> 6, n = k & 63;
    uint32_t byte = (uint32_t)n * 512u + (uint32_t)dp * 4u;
    byte ^= (uint32_t)(n & 7) << 4;
    *(unsigned*)(g_btiles + (uint32_t)tile * TILE_BYTES + byte) = packh(c0, c1);
}

// ---------------------------------------------------------------- kernel 3: collect unique valid ids
__global__ void compact_kernel(const int* __restrict__ ids, const int* __restrict__ msk) {
    int r = blockIdx.x * blockDim.x + threadIdx.x;
    if (r >= NROWS) return;
    if (msk[r] >= 1) {
        int id = ids[r];
        if (atomicExch(&g_mark[id], 1) == 0) {
            int pos = atomicAdd(&g_nuniq, 1);
            g_uniq[pos] = id;
        }
    }
}

// ---------------------------------------------------------------- kernel 4: fp16 HMMA argmin (unique ids)
// acc[u][n] = <e_u, c_n>; dist = ||c||^2 - 2*acc; top-4 per id; exact rescore later.
__global__ void __launch_bounds__(256, 2)
argmin_mma(const float* __restrict__ emb)
{
    extern __shared__ char smem[];
    const uint32_t sb  = smem_u32(smem);
    const int tid = threadIdx.x;
    const int l   = tid & 31;
    const int w   = tid >> 5;
    const int r0  = blockIdx.x * MT;
    const int nuniq = g_nuniq;
    if (r0 >= nuniq) return;                    // whole-CTA early exit
    float* s_cn  = (float*)(smem + SO_CN);
    int*   s_map = (int*)(smem + SO_MAP);

    if (tid == 0) { MBAR_INIT(sb + SO_BAR + 0, 1); MBAR_INIT(sb + SO_BAR + 8, 1); }

    // ---- stage A rows (fp16) into the B-buffer region temporarily
    {
        const int row  = tid >> 1, half = tid & 1;
        int u = r0 + row; if (u >= nuniq) u = nuniq - 1;   // tail duplicates
        const int id = g_uniq[u];
        if (half == 0) s_map[row] = id;
        const float4* ep = (const float4*)(emb + (size_t)id * DIMN + half * 128);
        const uint32_t rowbase = (uint32_t)row * 512u;
        const uint32_t hb = (uint32_t)half * 256u;
        const uint32_t xo = (uint32_t)(row & 7) << 4;
#pragma unroll
        for (int q = 0; q < 32; q++) {
            float4 v = ep[q];
            uint32_t off = rowbase + ((hb + (uint32_t)q * 8u) ^ xo);
            *(unsigned*)(smem + SO_B + off)     = packh(v.x, v.y);
            *(unsigned*)(smem + SO_B + off + 4) = packh(v.z, v.w);
        }
        for (int i = tid; i < KCODE; i += 256) s_cn[i] = g_cnorm[i];
    }
    __syncthreads();

    // ---- fragment address constants
    const uint32_t xorv   = (uint32_t)(l & 7) << 4;
    const uint32_t arow   = (uint32_t)(w * 16 + (l & 7) + ((l >> 3) & 1) * 8);
    const uint32_t koff_a = (uint32_t)((l >> 4) & 1) * 16u;
    const uint32_t jpoff  = (uint32_t)((l >> 4) & 1) * 4096u + (uint32_t)(l & 7) * 512u;
    const uint32_t koff_b = (uint32_t)((l >> 3) & 1) * 16u;

    // ---- A fragments -> persistent registers (64 regs)
    unsigned ah[16][4];
    {
        const uint32_t a_b = sb + SO_B + arow * 512u;
#pragma unroll
        for (int s = 0; s < 16; s++)
            LDSM_X4(ah[s], a_b + (((uint32_t)(s * 32) + koff_a) ^ xorv));
    }
    __syncthreads();   // staging free -> becomes B double buffer

    if (tid == 0) {
        MBAR_EXPECT_TX(sb + SO_BAR + 0, TILE_BYTES);
        BULK_G2S(sb + SO_B, (const void*)g_btiles, TILE_BYTES, sb + SO_BAR + 0);
        MBAR_EXPECT_TX(sb + SO_BAR + 8, TILE_BYTES);
        BULK_G2S(sb + SO_B + TILE_BYTES, (const void*)(g_btiles + TILE_BYTES),
                 TILE_BYTES, sb + SO_BAR + 8);
    }

    float acc[8][4];
#pragma unroll
    for (int j = 0; j < 8; j++)
#pragma unroll
        for (int e = 0; e < 4; e++) acc[j][e] = 0.f;

    float v4[2][4]; int ix4[2][4];
#pragma unroll
    for (int rr = 0; rr < 2; rr++)
#pragma unroll
        for (int q = 0; q < 4; q++) { v4[rr][q] = 3.4e38f; ix4[rr][q] = 0x7fffffff; }

    int par[2] = {0, 0};

    for (int t = 0; t < NT; t++) {
        const int buf = t & 1;
        const uint32_t Bb = sb + SO_B + (uint32_t)buf * TILE_BYTES;
        MBAR_WAIT(sb + SO_BAR + 8 * buf, (uint32_t)par[buf]); par[buf] ^= 1;

#pragma unroll
        for (int s = 0; s < 16; s++) {
            const uint32_t kx = ((uint32_t)(s * 32) + koff_b) ^ xorv;
#pragma unroll
            for (int p = 0; p < 4; p++) {        // p covers code pairs (2p, 2p+1)
                unsigned b4[4];
                LDSM_X4(b4, Bb + jpoff + (uint32_t)p * 8192u + kx);
                mma_f16(acc[2 * p],     ah[s], b4);
                mma_f16(acc[2 * p + 1], ah[s], b4 + 2);
            }
        }

        // epilogue: dist = ||c||^2 - 2*acc; top-4 per row (guarded insert)
        const int cbase = t * NTIL;
#pragma unroll
        for (int j = 0; j < 8; j++) {
#pragma unroll
            for (int e = 0; e < 4; e++) {
                const int rr   = e >> 1;
                const int code = cbase + j * 8 + 2 * (l & 3) + (e & 1);
                const float dist = fmaf(-2.0f, acc[j][e], s_cn[code]);
                if (dist < v4[rr][3]) ins4(dist, code, v4[rr], ix4[rr]);
                acc[j][e] = 0.f;
            }
        }
        __syncthreads();
        if (tid == 0 && t + 2 < NT) {
            MBAR_EXPECT_TX(sb + SO_BAR + 8 * buf, TILE_BYTES);
            BULK_G2S(Bb, (const void*)(g_btiles + (size_t)(t + 2) * TILE_BYTES),
                     TILE_BYTES, sb + SO_BAR + 8 * buf);
        }
    }

    // ---- merge top-4 across the 4 lanes sharing each row
#pragma unroll
    for (int rr = 0; rr < 2; rr++) {
#pragma unroll
        for (int off = 1; off <= 2; off <<= 1) {
            float ov[4]; int oi[4];
#pragma unroll
            for (int q = 0; q < 4; q++) {
                ov[q] = __shfl_xor_sync(0xffffffffu, v4[rr][q], off);
                oi[q] = __shfl_xor_sync(0xffffffffu, ix4[rr][q], off);
            }
#pragma unroll
            for (int q = 0; q < 4; q++) ins4(ov[q], oi[q], v4[rr], ix4[rr]);
        }
        if ((l & 3) == 0) {
            const int id = s_map[w * 16 + (l >> 2) + rr * 8];
            g_ridx[id]  = ix4[rr][0];
            g_rmeta[id] = make_float2(v4[rr][0], v4[rr][1]);
            g_rcand[id] = make_int4(ix4[rr][0], ix4[rr][1], ix4[rr][2], ix4[rr][3]);
        }
    }
}

// ---------------------------------------------------------------- kernel 5: c0 = argmin ||c||^2
__global__ void prep_kernel() {
    __shared__ float sv[8];
    __shared__ int   si[8];
    int tid = threadIdx.x;
    float v = 3.4e38f; int ix = 0x7fffffff;
    for (int i = tid; i < KCODE; i += 256) {
        float c = g_cnorm[i];
        if (c < v || (c == v && i < ix)) { v = c; ix = i; }
    }
#pragma unroll
    for (int o = 16; o; o >>= 1) {
        float ov = __shfl_xor_sync(0xffffffffu, v, o);
        int   oi = __shfl_xor_sync(0xffffffffu, ix, o);
        if (ov < v || (ov == v && oi < ix)) { v = ov; ix = oi; }
    }
    if ((tid & 31) == 0) { sv[tid >> 5] = v; si[tid >> 5] = ix; }
    __syncthreads();
    if (tid == 0) {
#pragma unroll
        for (int q = 1; q < 8; q++)
            if (sv[q] < v || (sv[q] == v && si[q] < ix)) { v = sv[q]; ix = si[q]; }
        g_c0 = ix;
    }
}

// ---------------------------------------------------------------- kernel 6: exact fp32 rescore of near-ties
__global__ void rescore_kernel(const float* __restrict__ emb, const float* __restrict__ cb)
{
    int u = blockIdx.x * blockDim.x + threadIdx.x;
    if (u >= g_nuniq) return;
    const int id = g_uniq[u];
    float2 m = g_rmeta[id];
    if (m.y - m.x >= TAU) return;
    int4 cd = g_rcand[id];
    const int cods[4] = {cd.x, cd.y, cd.z, cd.w};
    const float* e = emb + (size_t)id * DIMN;

    float bestd = 3.4e38f; int besti = 0x7fffffff;
#pragma unroll
    for (int q = 0; q < 4; q++) {
        const int c = cods[q];
        const float* cp = cb + (size_t)c * DIMN;
        float a = 0.f, b = 0.f;
#pragma unroll 4
        for (int k = 0; k < DIMN; k += 2) {
            a = fmaf(e[k],     cp[k],     a);
            b = fmaf(e[k + 1], cp[k + 1], b);
        }
        float d = fmaf(-2.0f, a + b, g_cnorm[c]);
        if (d < bestd || (d == bestd && c < besti)) { bestd = d; besti = c; }
    }
    g_ridx[id] = besti;
}

// ---------------------------------------------------------------- kernel 7: means + encoder dense
__global__ void __launch_bounds__(256)
finish_kernel(const int* __restrict__ ids, const int* __restrict__ msk,
              const float* __restrict__ emb, const float* __restrict__ cb,
              const float* __restrict__ W,   const float* __restrict__ bias,
              float* __restrict__ out)
{
    __shared__ int   s_id[LL];
    __shared__ float s_m[LL];
    __shared__ int   s_vq[LL];
    __shared__ float s_x[2 * DIMN];
    __shared__ int   s_cnt;

    const int b = blockIdx.x, tid = threadIdx.x;
    if (tid == 0) s_cnt = 0;
    __syncthreads();
    if (tid < LL) {
        int   id = ids[b * LL + tid];
        int   mv = msk[b * LL + tid];
        float m  = (mv >= 1) ? 1.f : 0.f;
        s_id[tid] = id;
        s_m[tid]  = m;
        s_vq[tid] = (mv >= 1) ? g_ridx[id] : g_c0;
        if (m > 0.f) atomicAdd(&s_cnt, 1);
    }
    __syncthreads();

    const float cnt = (float)s_cnt;
    const int   d   = tid;
    float hist = 0.f, vq = 0.f;
#pragma unroll 4
    for (int ll = 0; ll < LL; ll++) {
        hist = fmaf(emb[(size_t)s_id[ll] * DIMN + d], s_m[ll], hist);
        vq  += cb[(size_t)s_vq[ll] * DIMN + d];
    }
    s_x[d]        = vq / cnt;
    s_x[DIMN + d] = hist / (cnt + 1e-9f);
    __syncthreads();

    float a0 = bias[d], a1 = 0.f;
#pragma unroll 8
    for (int i = 0; i < DIMN; i++) {
        a0 = fmaf(s_x[i],        W[(size_t)i * DIMN + d],          a0);
        a1 = fmaf(s_x[DIMN + i], W[(size_t)(DIMN + i) * DIMN + d], a1);
    }
    out[(size_t)b * DIMN + d] = a0 + a1;
}

// ----------------------------------------------------------------
extern "C" void kernel_launch(void* const* d_in, const int* in_sizes, int n_in,
                              void* d_out, int out_size)
{
    const int*   ids  = (const int*)  d_in[0];
    const int*   msk  = (const int*)  d_in[1];
    const float* emb  = (const float*)d_in[2];
    const float* cb   = (const float*)d_in[3];
    const float* W    = (const float*)d_in[4];
    const float* bias = (const float*)d_in[5];
    float*       out  = (float*)d_out;

    cudaFuncSetAttribute(argmin_mma,
                         cudaFuncAttributeMaxDynamicSharedMemorySize, SMEM_TOTAL);

    cnorm_kernel<<<KCODE / 8, 256>>>(cb);                       // 1
    bsplit_kernel<<<(KCODE * (DIMN / 2)) / 256, 256>>>(cb);     // 2 (also resets dedup state)
    compact_kernel<<<(NROWS + 255) / 256, 256>>>(ids, msk);     // 3
    argmin_mma<<<MAXCTA, 256, SMEM_TOTAL>>>(emb);               // 4  <- ncu slot
    prep_kernel<<<1, 256>>>();                                  // 5
    rescore_kernel<<<(VOCAB + 255) / 256, 256>>>(emb, cb);      // 6
    finish_kernel<<<BB, 256>>>(ids, msk, emb, cb, W, bias, out);// 7
}